// round 6
// baseline (speedup 1.0000x reference)
#include <cuda_runtime.h>

#define KK     3
#define CIN    16
#define COUT   16
#define HH     64
#define WW     64
#define BB     4

#define TILE_H 4          // output rows per block
#define BX     64
#define BY     4          // 256 threads: ty>>1 = c-half, ty&1 = pixel-pair
#define PX     2          // pixels (rows) per thread
#define FG     2          // output channels per block (1 packed f32x2 pair)
#define CHALF  8          // input channels per c-half

#define SX_ROWS (TILE_H + 2)                 // 6

typedef unsigned long long ull;

// ---------------- Blackwell packed f32x2 helpers ----------------
__device__ __forceinline__ ull pk2s(float v) {            // (v, v)
    ull r; asm("mov.b64 %0, {%1, %1};" : "=l"(r) : "f"(v)); return r;
}
__device__ __forceinline__ void upk2(ull v, float& lo, float& hi) {
    asm("mov.b64 {%0, %1}, %2;" : "=f"(lo), "=f"(hi) : "l"(v));
}
__device__ __forceinline__ ull pk2(float lo, float hi) {
    ull r; asm("mov.b64 %0, {%1, %2};" : "=l"(r) : "f"(lo), "f"(hi)); return r;
}
__device__ __forceinline__ ull ffma2(ull a, ull b, ull c) {
    ull d; asm("fma.rn.f32x2 %0, %1, %2, %3;" : "=l"(d) : "l"(a), "l"(b), "l"(c)); return d;
}
__device__ __forceinline__ ull fmul2(ull a, ull b) {
    ull d; asm("mul.rn.f32x2 %0, %1, %2;" : "=l"(d) : "l"(a), "l"(b)); return d;
}
__device__ __forceinline__ ull fadd2(ull a, ull b) {
    ull d; asm("add.rn.f32x2 %0, %1, %2;" : "=l"(d) : "l"(a), "l"(b)); return d;
}
__device__ __forceinline__ float frcp(float x) {
    float r; asm("rcp.approx.ftz.f32 %0, %1;" : "=f"(r) : "f"(x)); return r;
}

// Static SMEM (38.9 KB):
//  sC:   packed coefficients, f-pair x all 16 input channels:
//        per (c,p): 10 float2 (6 A-pairs, 4 B-pairs) -> 1440 float2 = 11520 B
//  sX:   16 input-channel tiles, 6 rows x 66 cols = 25344 B
//  sRed: cross-c-half reduction buffer, 128 threads x 2 accs = 2048 B
__global__ __launch_bounds__(BX * BY)
void kaconv_kernel(const float* __restrict__ x,
                   const float* __restrict__ A,
                   const float* __restrict__ Bc,
                   float* __restrict__ out) {
    __shared__ __align__(16) ull  sC[CIN * 9 * 10];      // 1440 slots
    __shared__ float              sX[CIN * SX_ROWS * 66];
    __shared__ ull                sRed[BX * 2 * 2];       // [pyg][tx][2]

    const int tx  = threadIdx.x;
    const int ty  = threadIdx.y;
    const int tid = ty * BX + tx;
    const int h0  = blockIdx.x * TILE_H;
    const int b   = blockIdx.y;
    const int f0  = blockIdx.z * FG;
    const int ch  = ty >> 1;                 // c-half: 0 or 1
    const int pyg = ty & 1;                  // pixel-pair group: 0 or 1
    const int c0  = ch * CHALF;

    // ---- stage packed coefficients (all 16 channels) ----
    float2* sCf = reinterpret_cast<float2*>(sC);
    for (int i = tid; i < CIN * 9 * 10; i += BX * BY) {
        int ii = i;
        const int k = ii % 10; ii /= 10;
        const int p = ii % 9;
        const int c = ii / 9;
        float lo, hi;
        if (k < 6) {
            lo = A[(( f0      * CIN + c) * 9 + p) * 6 + k];
            hi = A[(((f0 + 1) * CIN + c) * 9 + p) * 6 + k];
        } else {
            const int j = k - 6;
            lo = Bc[(( f0      * CIN + c) * 9 + p) * 4 + j];
            hi = Bc[(((f0 + 1) * CIN + c) * 9 + p) * 4 + j];
        }
        sCf[i] = make_float2(lo, hi);
    }

    // ---- stage all 16 input-channel tiles with zero-padded halo ----
    for (int i = tid; i < CIN * SX_ROWS * 66; i += BX * BY) {
        const int col = i % 66;
        const int r   = (i / 66) % SX_ROWS;
        const int c   = i / (66 * SX_ROWS);
        const int gh  = h0 + r - 1;
        const int gw  = col - 1;
        float v = 0.0f;
        if (gh >= 0 && gh < HH && gw >= 0 && gw < WW)
            v = x[((b * CIN + c) * HH + gh) * WW + gw];
        sX[(c * SX_ROWS + r) * 66 + col] = v;
    }
    __syncthreads();

    const ulonglong2* sC2 = reinterpret_cast<const ulonglong2*>(sC);
    const ull ABSM = 0x7FFFFFFF7FFFFFFFull;
    const ull ONE2 = 0x3F8000003F800000ull;   // (1.0f, 1.0f)

    ull acc0 = 0ull, acc1 = 0ull;             // 2 pixels, packed f-pair

    #pragma unroll 1
    for (int cl = 0; cl < CHALF; cl++) {
        const int c = c0 + cl;
        // 4 rows x 3 cols register window covers both pixels' 3x3 windows
        float xr[PX + 2][3];
        #pragma unroll
        for (int r = 0; r < PX + 2; r++)
            #pragma unroll
            for (int j = 0; j < 3; j++)
                xr[r][j] = sX[(c * SX_ROWS + PX * pyg + r) * 66 + (tx + j)];

        const ulonglong2* pc = sC2 + c * 45;   // 5 ulonglong2 per (c,p)
        #pragma unroll
        for (int p = 0; p < 9; p++) {
            const int di = p / 3, dj = p % 3;
            const ulonglong2 u0 = pc[p * 5 + 0];  // {A0, A1}
            const ulonglong2 u1 = pc[p * 5 + 1];  // {A2, A3}
            const ulonglong2 u2 = pc[p * 5 + 2];  // {A4, A5}
            const ulonglong2 u3 = pc[p * 5 + 3];  // {B1, B2}
            const ulonglong2 u4 = pc[p * 5 + 4];  // {B3, B4}

            #pragma unroll
            for (int py = 0; py < PX; py++) {
                const ull X = pk2s(xr[py + di][dj]);

                // P = a0 + a1 x + ... + a5 x^5  (Horner, packed over f-pair)
                ull P = ffma2(u2.y, X, u2.x);
                P = ffma2(P, X, u1.y);
                P = ffma2(P, X, u1.x);
                P = ffma2(P, X, u0.y);
                P = ffma2(P, X, u0.x);

                // S = x*(b1 + x*(b2 + x*(b3 + x*b4)))
                ull T = ffma2(u4.y, X, u4.x);
                T = ffma2(T, X, u3.y);
                T = ffma2(T, X, u3.x);
                T = fmul2(T, X);

                // Q = 1 + |S|; R = 1/Q (per scalar via MUFU)
                const ull Qp = fadd2(ONE2, T & ABSM);
                float q0f, q1f; upk2(Qp, q0f, q1f);
                const ull R = pk2(frcp(q0f), frcp(q1f));

                if (py == 0) acc0 = ffma2(P, R, acc0);
                else         acc1 = ffma2(P, R, acc1);
            }
        }
    }

    // ---- in-block combine across the two c-halves ----
    if (ch == 1) {
        sRed[(pyg * BX + tx) * 2 + 0] = acc0;
        sRed[(pyg * BX + tx) * 2 + 1] = acc1;
    }
    __syncthreads();
    if (ch == 0) {
        const ull o0 = fadd2(acc0, sRed[(pyg * BX + tx) * 2 + 0]);
        const ull o1 = fadd2(acc1, sRed[(pyg * BX + tx) * 2 + 1]);

        const int hA = h0 + PX * pyg;
        const int w  = tx;
        float a0, a1, b0, b1;
        upk2(o0, a0, a1);   // pixel row hA,   channels f0 / f0+1
        upk2(o1, b0, b1);   // pixel row hA+1, channels f0 / f0+1
        float* op = out + ((b * COUT + f0) * HH + hA) * WW + w;
        op[0]                = a0;
        op[WW]               = b0;
        op[HH * WW]          = a1;
        op[HH * WW + WW]     = b1;
    }
}

extern "C" void kernel_launch(void* const* d_in, const int* in_sizes, int n_in,
                              void* d_out, int out_size) {
    const float* x  = (const float*)d_in[0];
    const float* A  = (const float*)d_in[1];
    const float* Bc = (const float*)d_in[2];
    float* out = (float*)d_out;

    dim3 grid(HH / TILE_H, BB, COUT / FG);   // (16, 4, 8) = 512 blocks
    dim3 block(BX, BY, 1);                   // 256 threads
    kaconv_kernel<<<grid, block>>>(x, A, Bc, out);
}

// round 7
// speedup vs baseline: 1.0655x; 1.0655x over previous
#include <cuda_runtime.h>

#define KK     3
#define CIN    16
#define COUT   16
#define HH     64
#define WW     64
#define BB     4

#define TILE_H 2          // output rows per block
#define BX     64
#define BY     2          // 128 threads: ty = c-half
#define PX     2          // pixels (rows) per thread
#define FG     2          // output channels per block (1 packed f32x2 pair)
#define CHALF  8          // input channels per c-half

#define SX_ROWS (TILE_H + 2)                 // 4

typedef unsigned long long ull;

// ---------------- Blackwell packed f32x2 helpers ----------------
__device__ __forceinline__ ull pk2s(float v) {            // (v, v)
    ull r; asm("mov.b64 %0, {%1, %1};" : "=l"(r) : "f"(v)); return r;
}
__device__ __forceinline__ void upk2(ull v, float& lo, float& hi) {
    asm("mov.b64 {%0, %1}, %2;" : "=f"(lo), "=f"(hi) : "l"(v));
}
__device__ __forceinline__ ull pk2(float lo, float hi) {
    ull r; asm("mov.b64 %0, {%1, %2};" : "=l"(r) : "f"(lo), "f"(hi)); return r;
}
__device__ __forceinline__ ull ffma2(ull a, ull b, ull c) {
    ull d; asm("fma.rn.f32x2 %0, %1, %2, %3;" : "=l"(d) : "l"(a), "l"(b), "l"(c)); return d;
}
__device__ __forceinline__ ull fmul2(ull a, ull b) {
    ull d; asm("mul.rn.f32x2 %0, %1, %2;" : "=l"(d) : "l"(a), "l"(b)); return d;
}
__device__ __forceinline__ ull fadd2(ull a, ull b) {
    ull d; asm("add.rn.f32x2 %0, %1, %2;" : "=l"(d) : "l"(a), "l"(b)); return d;
}
__device__ __forceinline__ float frcp(float x) {
    float r; asm("rcp.approx.ftz.f32 %0, %1;" : "=f"(r) : "f"(x)); return r;
}

// Static SMEM (29.4 KB):
//  sC:   packed coefficients, f-pair x all 16 input channels:
//        per (c,p): 10 float2 (6 A-pairs, 4 B-pairs) -> 1440 float2 = 11520 B
//  sX:   16 input-channel tiles, 4 rows x 66 cols = 16896 B
//  sRed: cross-c-half reduction buffer, 64 threads x 2 accs = 1024 B
__global__ __launch_bounds__(BX * BY)
void kaconv_kernel(const float* __restrict__ x,
                   const float* __restrict__ A,
                   const float* __restrict__ Bc,
                   float* __restrict__ out) {
    __shared__ __align__(16) ull  sC[CIN * 9 * 10];      // 1440 slots
    __shared__ float              sX[CIN * SX_ROWS * 66];
    __shared__ ull                sRed[BX * 2];           // [tx][2 accs]

    const int tx  = threadIdx.x;
    const int ty  = threadIdx.y;                          // c-half
    const int tid = ty * BX + tx;
    const int h0  = blockIdx.x * TILE_H;
    const int b   = blockIdx.y;
    const int f0  = blockIdx.z * FG;
    const int c0  = ty * CHALF;

    // ---- stage packed coefficients (all 16 channels, f-pair) ----
    float2* sCf = reinterpret_cast<float2*>(sC);
    for (int i = tid; i < CIN * 9 * 10; i += BX * BY) {
        int ii = i;
        const int k = ii % 10; ii /= 10;
        const int p = ii % 9;
        const int c = ii / 9;
        float lo, hi;
        if (k < 6) {
            lo = A[(( f0      * CIN + c) * 9 + p) * 6 + k];
            hi = A[(((f0 + 1) * CIN + c) * 9 + p) * 6 + k];
        } else {
            const int j = k - 6;
            lo = Bc[(( f0      * CIN + c) * 9 + p) * 4 + j];
            hi = Bc[(((f0 + 1) * CIN + c) * 9 + p) * 4 + j];
        }
        sCf[i] = make_float2(lo, hi);
    }

    // ---- stage all 16 input-channel tiles with zero-padded halo ----
    for (int i = tid; i < CIN * SX_ROWS * 66; i += BX * BY) {
        const int col = i % 66;
        const int r   = (i / 66) % SX_ROWS;
        const int c   = i / (66 * SX_ROWS);
        const int gh  = h0 + r - 1;
        const int gw  = col - 1;
        float v = 0.0f;
        if (gh >= 0 && gh < HH && gw >= 0 && gw < WW)
            v = x[((b * CIN + c) * HH + gh) * WW + gw];
        sX[(c * SX_ROWS + r) * 66 + col] = v;
    }
    __syncthreads();

    const ulonglong2* sC2 = reinterpret_cast<const ulonglong2*>(sC);

    ull acc0 = 0ull, acc1 = 0ull;             // 2 pixels, packed f-pair

    #pragma unroll 1
    for (int cl = 0; cl < CHALF; cl++) {
        const int c = c0 + cl;
        // 4 rows x 3 cols register window covers both pixels' 3x3 windows
        float xr[PX + 2][3];
        #pragma unroll
        for (int r = 0; r < PX + 2; r++)
            #pragma unroll
            for (int j = 0; j < 3; j++)
                xr[r][j] = sX[(c * SX_ROWS + r) * 66 + (tx + j)];

        const ulonglong2* pc = sC2 + c * 45;   // 5 ulonglong2 per (c,p)
        #pragma unroll
        for (int p = 0; p < 9; p++) {
            const int di = p / 3, dj = p % 3;
            const ulonglong2 u0 = pc[p * 5 + 0];  // {A0, A1}
            const ulonglong2 u1 = pc[p * 5 + 1];  // {A2, A3}
            const ulonglong2 u2 = pc[p * 5 + 2];  // {A4, A5}
            const ulonglong2 u3 = pc[p * 5 + 3];  // {B1, B2}
            const ulonglong2 u4 = pc[p * 5 + 4];  // {B3, B4}

            #pragma unroll
            for (int py = 0; py < PX; py++) {
                const ull X = pk2s(xr[py + di][dj]);

                // P = a0 + a1 x + ... + a5 x^5  (Horner, packed over f-pair)
                ull P = ffma2(u2.y, X, u2.x);
                P = ffma2(P, X, u1.y);
                P = ffma2(P, X, u1.x);
                P = ffma2(P, X, u0.y);
                P = ffma2(P, X, u0.x);

                // S = x*(b1 + x*(b2 + x*(b3 + x*b4)))
                ull T = ffma2(u4.y, X, u4.x);
                T = ffma2(T, X, u3.y);
                T = ffma2(T, X, u3.x);
                T = fmul2(T, X);

                // Q = 1 + |S| per scalar (abs is a free operand modifier),
                // R = 1/Q via MUFU; repack for the packed accumulate.
                float t0, t1; upk2(T, t0, t1);
                const float r0 = frcp(1.0f + fabsf(t0));
                const float r1 = frcp(1.0f + fabsf(t1));
                const ull R = pk2(r0, r1);

                if (py == 0) acc0 = ffma2(P, R, acc0);
                else         acc1 = ffma2(P, R, acc1);
            }
        }
    }

    // ---- in-block combine across the two c-halves ----
    if (ty == 1) {
        sRed[tx * 2 + 0] = acc0;
        sRed[tx * 2 + 1] = acc1;
    }
    __syncthreads();
    if (ty == 0) {
        const ull o0 = fadd2(acc0, sRed[tx * 2 + 0]);
        const ull o1 = fadd2(acc1, sRed[tx * 2 + 1]);

        const int w = tx;
        float a0, a1, b0, b1;
        upk2(o0, a0, a1);   // pixel row h0,   channels f0 / f0+1
        upk2(o1, b0, b1);   // pixel row h0+1, channels f0 / f0+1
        float* op = out + ((b * COUT + f0) * HH + h0) * WW + w;
        op[0]                = a0;
        op[WW]               = b0;
        op[HH * WW]          = a1;
        op[HH * WW + WW]     = b1;
    }
}

extern "C" void kernel_launch(void* const* d_in, const int* in_sizes, int n_in,
                              void* d_out, int out_size) {
    const float* x  = (const float*)d_in[0];
    const float* A  = (const float*)d_in[1];
    const float* Bc = (const float*)d_in[2];
    float* out = (float*)d_out;

    dim3 grid(HH / TILE_H, BB, COUT / FG);   // (32, 4, 8) = 1024 blocks
    dim3 block(BX, BY, 1);                   // 128 threads
    kaconv_kernel<<<grid, block>>>(x, A, Bc, out);
}